// round 3
// baseline (speedup 1.0000x reference)
#include <cuda_runtime.h>
#include <math.h>

#define N_COLS 4096
#define TPB    256
#define EPS    1e-14f

// Persistent, pipelined Householder:
// out[r,i] = x[r,i] - (2*(x[r].v)/(||v||+eps)^2) * v[i] + bias[i]
// Each block owns v (registers) and a precomputed scalar s2 = 2/(||v||+eps)^2,
// then streams many rows with next-row loads issued before the dot reduction.
__global__ void __launch_bounds__(TPB, 3)
householder_kernel(const float* __restrict__ x,
                   const float* __restrict__ v,
                   const float* __restrict__ bias,
                   float* __restrict__ out,
                   int n_rows) {
    const int tid = threadIdx.x;
    const int w = tid >> 5, l = tid & 31;
    const float4* __restrict__ vr = (const float4*)v;
    const float4* __restrict__ br = (const float4*)bias;

    __shared__ float red[2][TPB / 32];
    __shared__ float s2_sh;

    // ---- once per block: v into registers, ||v||^2, scalar ----
    float4 vv[4];
    float vn = 0.0f;
    #pragma unroll
    for (int j = 0; j < 4; j++) {
        vv[j] = vr[tid + j * TPB];
        vn = fmaf(vv[j].x, vv[j].x, vn);
        vn = fmaf(vv[j].y, vv[j].y, vn);
        vn = fmaf(vv[j].z, vv[j].z, vn);
        vn = fmaf(vv[j].w, vv[j].w, vn);
    }
    #pragma unroll
    for (int o = 16; o > 0; o >>= 1)
        vn += __shfl_xor_sync(0xffffffffu, vn, o);
    if (l == 0) red[0][w] = vn;
    __syncthreads();
    if (tid == 0) {
        float t = 0.0f;
        #pragma unroll
        for (int i = 0; i < TPB / 32; i++) t += red[0][i];
        float s = 1.0f / (sqrtf(t) + EPS);
        s2_sh = 2.0f * s * s;            // fold the 2.0 here
    }
    __syncthreads();
    const float s2 = s2_sh;

    // ---- persistent row loop, double-buffered loads ----
    int row = blockIdx.x;
    const int stride = gridDim.x;
    if (row >= n_rows) return;

    float4 cur[4];
    {
        const float4* __restrict__ xr = (const float4*)(x + (size_t)row * N_COLS);
        #pragma unroll
        for (int j = 0; j < 4; j++) cur[j] = xr[tid + j * TPB];
    }

    int parity = 0;
    for (;;) {
        const int next = row + stride;
        const bool has_next = next < n_rows;

        // Prefetch next row BEFORE the reduction — hides DRAM latency
        // behind the shuffle chain + barrier.
        float4 nxt[4];
        if (has_next) {
            const float4* __restrict__ xr = (const float4*)(x + (size_t)next * N_COLS);
            #pragma unroll
            for (int j = 0; j < 4; j++) nxt[j] = xr[tid + j * TPB];
        }

        float dot = 0.0f;
        #pragma unroll
        for (int j = 0; j < 4; j++) {
            dot = fmaf(cur[j].x, vv[j].x, dot);
            dot = fmaf(cur[j].y, vv[j].y, dot);
            dot = fmaf(cur[j].z, vv[j].z, dot);
            dot = fmaf(cur[j].w, vv[j].w, dot);
        }
        #pragma unroll
        for (int o = 16; o > 0; o >>= 1)
            dot += __shfl_xor_sync(0xffffffffu, dot, o);
        if (l == 0) red[parity][w] = dot;
        __syncthreads();                   // the ONLY barrier per row
        float t = 0.0f;
        #pragma unroll
        for (int i = 0; i < TPB / 32; i++) t += red[parity][i];  // broadcast LDS
        const float coef = t * s2;

        float4* __restrict__ orow = (float4*)(out + (size_t)row * N_COLS);
        #pragma unroll
        for (int j = 0; j < 4; j++) {
            const int idx = tid + j * TPB;
            float4 bb = br[idx];           // L1/L2-hot
            float4 o4;
            o4.x = fmaf(-coef, vv[j].x, cur[j].x) + bb.x;
            o4.y = fmaf(-coef, vv[j].y, cur[j].y) + bb.y;
            o4.z = fmaf(-coef, vv[j].z, cur[j].z) + bb.z;
            o4.w = fmaf(-coef, vv[j].w, cur[j].w) + bb.w;
            orow[idx] = o4;
        }

        if (!has_next) break;
        #pragma unroll
        for (int j = 0; j < 4; j++) cur[j] = nxt[j];
        row = next;
        parity ^= 1;
    }
}

extern "C" void kernel_launch(void* const* d_in, const int* in_sizes, int n_in,
                              void* d_out, int out_size) {
    const float* x    = (const float*)d_in[0];   // [16384, 4096]
    const float* v    = (const float*)d_in[1];   // [4096, 1]
    const float* bias = (const float*)d_in[2];   // [4096]
    float* out = (float*)d_out;

    const int n_rows = in_sizes[0] / N_COLS;     // 16384

    int grid = 3 * 152;                          // 3 blocks/SM * 152 SMs (GB300)
    if (grid > n_rows) grid = n_rows;

    householder_kernel<<<grid, TPB>>>(x, v, bias, out, n_rows);
}